// round 14
// baseline (speedup 1.0000x reference)
#include <cuda_runtime.h>

#define D_MODEL 1024
#define SEQ_T   2048
#define BATCH   4
#define NH      16
#define DH      64
#define NE      8
#define GH      128

// ---------------- static device scratch (no allocation allowed) ----------------
__device__ float g_pooled[BATCH * D_MODEL];
__device__ float g_gw[BATCH * NE];
__device__ float g_Weff[(size_t)3 * BATCH * D_MODEL * D_MODEL];   // ~50 MB
__device__ float g_beff[3 * BATCH * D_MODEL];
__device__ float g_Q[(size_t)BATCH * NH * SEQ_T * DH];
__device__ float g_K[(size_t)BATCH * NH * SEQ_T * DH];
__device__ float g_V[(size_t)BATCH * NH * SEQ_T * DH];
__device__ float g_ctx[(size_t)BATCH * SEQ_T * D_MODEL];

// ---------------- 1. mean pool over T ----------------
__global__ void pool_kernel(const float* __restrict__ x) {
    int idx = blockIdx.x * 256 + threadIdx.x;      // BATCH*D = 4096 threads
    int b = idx >> 10, c = idx & 1023;
    const float* p = x + (size_t)b * SEQ_T * D_MODEL + c;
    float s = 0.f;
    for (int t = 0; t < SEQ_T; t++) s += p[(size_t)t * D_MODEL];
    g_pooled[idx] = s * (1.0f / SEQ_T);
}

// ---------------- 2. gate MLP + softmax ----------------
__global__ void gate_kernel(const float* __restrict__ Wg1, const float* __restrict__ bg1,
                            const float* __restrict__ Wg2, const float* __restrict__ bg2) {
    int b = blockIdx.x;
    int j = threadIdx.x;     // 128 threads
    __shared__ float h[GH];
    __shared__ float lg[NE];
    const float* p = g_pooled + b * D_MODEL;
    const float* w = Wg1 + (size_t)j * D_MODEL;
    float s = bg1[j];
    for (int i = 0; i < D_MODEL; i++) s += p[i] * w[i];
    h[j] = fmaxf(s, 0.f);
    __syncthreads();
    if (j < NE) {
        float s2 = bg2[j];
        const float* w2 = Wg2 + j * GH;
        for (int i = 0; i < GH; i++) s2 += h[i] * w2[i];
        lg[j] = s2;
    }
    __syncthreads();
    if (j == 0) {
        float m = lg[0];
        for (int e = 1; e < NE; e++) m = fmaxf(m, lg[e]);
        float ex[NE], sum = 0.f;
        for (int e = 0; e < NE; e++) { ex[e] = expf(lg[e] - m); sum += ex[e]; }
        float inv = 1.0f / sum;
        for (int e = 0; e < NE; e++) g_gw[b * NE + e] = ex[e] * inv;
    }
}

// ---------------- 3. mix expert weights:  W_eff[p][b] = sum_e gw[b,e] * W_p[e] ----------------
__global__ void mix_w_kernel(const float* __restrict__ Wq, const float* __restrict__ Wk,
                             const float* __restrict__ Wv) {
    int proj = blockIdx.y;
    size_t i = (size_t)blockIdx.x * 256 + threadIdx.x;   // over D*D
    const float* W = (proj == 0) ? Wq : (proj == 1) ? Wk : Wv;
    __shared__ float sgw[BATCH * NE];
    if (threadIdx.x < BATCH * NE) sgw[threadIdx.x] = g_gw[threadIdx.x];
    __syncthreads();
    float a0 = 0, a1 = 0, a2 = 0, a3 = 0;
    const size_t DD = (size_t)D_MODEL * D_MODEL;
    for (int e = 0; e < NE; e++) {
        float w = W[(size_t)e * DD + i];
        a0 += sgw[0 * NE + e] * w;
        a1 += sgw[1 * NE + e] * w;
        a2 += sgw[2 * NE + e] * w;
        a3 += sgw[3 * NE + e] * w;
    }
    float* o = g_Weff + (size_t)proj * BATCH * DD + i;
    o[0 * DD] = a0; o[1 * DD] = a1; o[2 * DD] = a2; o[3 * DD] = a3;
}

__global__ void mix_b_kernel(const float* __restrict__ bq, const float* __restrict__ bk,
                             const float* __restrict__ bv) {
    int idx = blockIdx.x * 256 + threadIdx.x;   // 3*B*D = 12288
    int proj = idx / (BATCH * D_MODEL);
    int r = idx % (BATCH * D_MODEL);
    int b = r / D_MODEL, o = r % D_MODEL;
    const float* bias = (proj == 0) ? bq : (proj == 1) ? bk : bv;
    float s = 0.f;
    for (int e = 0; e < NE; e++) s += g_gw[b * NE + e] * bias[e * D_MODEL + o];
    g_beff[idx] = s;
}

// ---------------- 4. SGEMM:  C = A @ Bw^T + bias   (A [M,K] rm, Bw [N,K] rm) ----------------
// QKVMODE: per-batch (grid.z = b), out written in [b,h,t,d] layout into g_Q/g_K/g_V.
// else:    single GEMM g_ctx @ Wo^T + bo -> Cx (plain row-major).
template <bool QKVMODE>
__global__ __launch_bounds__(256) void sgemm_kernel(const float* __restrict__ X,
                                                    const float* __restrict__ Wx,
                                                    const float* __restrict__ bx,
                                                    float* __restrict__ Cx, int which) {
    const int M = QKVMODE ? SEQ_T : BATCH * SEQ_T;
    const int N = D_MODEL, K = D_MODEL;
    int z = blockIdx.z;
    const float *A, *Bw, *bias;
    float* Cout;
    if (QKVMODE) {
        A = X + (size_t)z * M * K;
        Bw = g_Weff + ((size_t)which * BATCH + z) * D_MODEL * D_MODEL;
        bias = g_beff + (which * BATCH + z) * D_MODEL;
        Cout = ((which == 0) ? g_Q : (which == 1) ? g_K : g_V) + (size_t)z * NH * SEQ_T * DH;
    } else {
        A = g_ctx; Bw = Wx; bias = bx; Cout = Cx;
    }

    __shared__ float As[8][128];
    __shared__ float Bs[8][128];
    int tid = threadIdx.x;
    int row0 = (tid / 16) * 8, col0 = (tid % 16) * 8;
    int rowg = blockIdx.y * 128, colg = blockIdx.x * 128;
    int lr = tid >> 1, lc = (tid & 1) * 4;
    const float* Aptr = A + (size_t)(rowg + lr) * K + lc;
    const float* Bptr = Bw + (size_t)(colg + lr) * K + lc;

    float acc[8][8];
#pragma unroll
    for (int i = 0; i < 8; i++)
#pragma unroll
        for (int j = 0; j < 8; j++) acc[i][j] = 0.f;

    for (int k0 = 0; k0 < K; k0 += 8) {
        float4 av = *(const float4*)(Aptr + k0);
        float4 bv = *(const float4*)(Bptr + k0);
        As[lc + 0][lr] = av.x; As[lc + 1][lr] = av.y; As[lc + 2][lr] = av.z; As[lc + 3][lr] = av.w;
        Bs[lc + 0][lr] = bv.x; Bs[lc + 1][lr] = bv.y; Bs[lc + 2][lr] = bv.z; Bs[lc + 3][lr] = bv.w;
        __syncthreads();
#pragma unroll
        for (int k = 0; k < 8; k++) {
            float a[8], b[8];
            *(float4*)(a + 0) = *(const float4*)&As[k][row0];
            *(float4*)(a + 4) = *(const float4*)&As[k][row0 + 4];
            *(float4*)(b + 0) = *(const float4*)&Bs[k][col0];
            *(float4*)(b + 4) = *(const float4*)&Bs[k][col0 + 4];
#pragma unroll
            for (int i = 0; i < 8; i++)
#pragma unroll
                for (int j = 0; j < 8; j++) acc[i][j] += a[i] * b[j];
        }
        __syncthreads();
    }

#pragma unroll
    for (int i = 0; i < 8; i++) {
        int m = rowg + row0 + i;
#pragma unroll
        for (int j = 0; j < 8; j++) {
            int n = colg + col0 + j;
            float v = acc[i][j] + bias[n];
            if (QKVMODE)
                Cout[((size_t)(n >> 6) * SEQ_T + m) * DH + (n & 63)] = v;
            else
                Cout[(size_t)m * N + n] = v;
        }
    }
}

// ---------------- 5. flash attention, 64x64 tiles, fp32 ----------------
__global__ __launch_bounds__(256) void flash_kernel() {
    extern __shared__ float sm[];
    float* Qs = sm;                 // [64][64]
    float* Ks = sm + 64 * 64;       // [64][65]  (reused as P after softmax)
    float* Vs = Ks + 64 * 65;       // [64][64]

    int bh = blockIdx.y;
    int q0 = blockIdx.x * 64;
    const float* Qg = g_Q + (size_t)bh * SEQ_T * DH;
    const float* Kg = g_K + (size_t)bh * SEQ_T * DH;
    const float* Vg = g_V + (size_t)bh * SEQ_T * DH;

    int tid = threadIdx.x, tx = tid % 16, ty = tid / 16;

    // load Q tile (64x64 floats, float4)
#pragma unroll
    for (int u = 0; u < 4; u++) {
        int e = tid + u * 256;          // float4 index: 1024 total
        int r = e >> 4, c4 = (e & 15) * 4;
        *(float4*)&Qs[r * 64 + c4] = *(const float4*)&Qg[(size_t)(q0 + r) * DH + c4];
    }

    float mrow[4], lrow[4];
    float oacc[4][4];
#pragma unroll
    for (int i = 0; i < 4; i++) {
        mrow[i] = -1e30f; lrow[i] = 0.f;
#pragma unroll
        for (int j = 0; j < 4; j++) oacc[i][j] = 0.f;
    }

    for (int kt = 0; kt < SEQ_T; kt += 64) {
        // load K (padded 65) and V (64) tiles
#pragma unroll
        for (int u = 0; u < 4; u++) {
            int e = tid + u * 256;
            int r = e >> 4, c4 = (e & 15) * 4;
            float4 kv = *(const float4*)&Kg[(size_t)(kt + r) * DH + c4];
            Ks[r * 65 + c4 + 0] = kv.x; Ks[r * 65 + c4 + 1] = kv.y;
            Ks[r * 65 + c4 + 2] = kv.z; Ks[r * 65 + c4 + 3] = kv.w;
            *(float4*)&Vs[r * 64 + c4] = *(const float4*)&Vg[(size_t)(kt + r) * DH + c4];
        }
        __syncthreads();

        // S = Q K^T (each thread 4x4)
        float s[4][4];
#pragma unroll
        for (int i = 0; i < 4; i++)
#pragma unroll
            for (int j = 0; j < 4; j++) s[i][j] = 0.f;
#pragma unroll 8
        for (int d = 0; d < DH; d++) {
            float qf[4], kf[4];
#pragma unroll
            for (int i = 0; i < 4; i++) qf[i] = Qs[(ty * 4 + i) * 64 + d];
#pragma unroll
            for (int j = 0; j < 4; j++) kf[j] = Ks[(tx * 4 + j) * 65 + d];
#pragma unroll
            for (int i = 0; i < 4; i++)
#pragma unroll
                for (int j = 0; j < 4; j++) s[i][j] += qf[i] * kf[j];
        }

        // online softmax (row reduce across tx = 16 lanes within half-warp)
#pragma unroll
        for (int i = 0; i < 4; i++) {
            float rm = -1e30f;
#pragma unroll
            for (int j = 0; j < 4; j++) {
                s[i][j] *= 0.125f;                 // 1/sqrt(64)
                rm = fmaxf(rm, s[i][j]);
            }
#pragma unroll
            for (int off = 8; off >= 1; off >>= 1)
                rm = fmaxf(rm, __shfl_xor_sync(0xffffffffu, rm, off));
            float mnew = fmaxf(mrow[i], rm);
            float corr = __expf(mrow[i] - mnew);
            float rs = 0.f;
#pragma unroll
            for (int j = 0; j < 4; j++) {
                s[i][j] = __expf(s[i][j] - mnew);
                rs += s[i][j];
            }
#pragma unroll
            for (int off = 8; off >= 1; off >>= 1)
                rs += __shfl_xor_sync(0xffffffffu, rs, off);
            lrow[i] = lrow[i] * corr + rs;
            mrow[i] = mnew;
#pragma unroll
            for (int j = 0; j < 4; j++) oacc[i][j] *= corr;
        }
        __syncthreads();   // everyone done reading Ks

        // write P into Ks buffer: Ps[r][c], stride 65
#pragma unroll
        for (int i = 0; i < 4; i++)
#pragma unroll
            for (int j = 0; j < 4; j++)
                Ks[(ty * 4 + i) * 65 + tx * 4 + j] = s[i][j];
        __syncthreads();

        // O += P @ V
#pragma unroll 8
        for (int c = 0; c < 64; c++) {
            float pf[4], vf[4];
#pragma unroll
            for (int i = 0; i < 4; i++) pf[i] = Ks[(ty * 4 + i) * 65 + c];
            *(float4*)vf = *(const float4*)&Vs[c * 64 + tx * 4];
#pragma unroll
            for (int i = 0; i < 4; i++)
#pragma unroll
                for (int j = 0; j < 4; j++) oacc[i][j] += pf[i] * vf[j];
        }
        __syncthreads();
    }

    // normalize + write context in [b, t, h*64+col] layout
    int b = bh >> 4, h = bh & 15;
#pragma unroll
    for (int i = 0; i < 4; i++) {
        float inv = 1.0f / lrow[i];
        int t = q0 + ty * 4 + i;
        float4 v;
        v.x = oacc[i][0] * inv; v.y = oacc[i][1] * inv;
        v.z = oacc[i][2] * inv; v.w = oacc[i][3] * inv;
        *(float4*)&g_ctx[(size_t)(b * SEQ_T + t) * D_MODEL + h * DH + tx * 4] = v;
    }
}

// ---------------- launch ----------------
extern "C" void kernel_launch(void* const* d_in, const int* in_sizes, int n_in,
                              void* d_out, int out_size) {
    const float* x   = (const float*)d_in[0];
    const float* Wq  = (const float*)d_in[1];
    const float* bq  = (const float*)d_in[2];
    const float* Wk  = (const float*)d_in[3];
    const float* bk  = (const float*)d_in[4];
    const float* Wv  = (const float*)d_in[5];
    const float* bv  = (const float*)d_in[6];
    const float* Wg1 = (const float*)d_in[7];
    const float* bg1 = (const float*)d_in[8];
    const float* Wg2 = (const float*)d_in[9];
    const float* bg2 = (const float*)d_in[10];
    const float* Wo  = (const float*)d_in[11];
    const float* bo  = (const float*)d_in[12];
    float* out = (float*)d_out;

    pool_kernel<<<16, 256>>>(x);
    gate_kernel<<<4, 128>>>(Wg1, bg1, Wg2, bg2);
    mix_w_kernel<<<dim3(4096, 3), 256>>>(Wq, Wk, Wv);
    mix_b_kernel<<<48, 256>>>(bq, bk, bv);

    for (int p = 0; p < 3; p++)
        sgemm_kernel<true><<<dim3(8, 16, 4), 256>>>(x, nullptr, nullptr, nullptr, p);

    int smem = (64 * 64 + 64 * 65 + 64 * 64) * 4;   // 49408 B
    cudaFuncSetAttribute(flash_kernel, cudaFuncAttributeMaxDynamicSharedMemorySize, smem);
    flash_kernel<<<dim3(SEQ_T / 64, BATCH * NH), 256, smem>>>();

    sgemm_kernel<false><<<dim3(8, 64, 1), 256>>>(nullptr, Wo, bo, out, 0);
}

// round 15
// speedup vs baseline: 1.0001x; 1.0001x over previous
#include <cuda_runtime.h>

#define D_MODEL 1024
#define SEQ_T   2048
#define BATCH   4
#define NH      16
#define DH      64
#define NE      8
#define GH      128

// ---------------- static device scratch (no allocation allowed) ----------------
__device__ float g_pooled[BATCH * D_MODEL];
__device__ float g_gw[BATCH * NE];
__device__ float g_Weff[(size_t)3 * BATCH * D_MODEL * D_MODEL];   // ~50 MB
__device__ float g_beff[3 * BATCH * D_MODEL];
__device__ float g_Q[(size_t)BATCH * NH * SEQ_T * DH];
__device__ float g_K[(size_t)BATCH * NH * SEQ_T * DH];
__device__ float g_V[(size_t)BATCH * NH * SEQ_T * DH];
__device__ float g_ctx[(size_t)BATCH * SEQ_T * D_MODEL];

// ---------------- 1. mean pool over T ----------------
__global__ void pool_kernel(const float* __restrict__ x) {
    int idx = blockIdx.x * 256 + threadIdx.x;      // BATCH*D = 4096 threads
    int b = idx >> 10, c = idx & 1023;
    const float* p = x + (size_t)b * SEQ_T * D_MODEL + c;
    float s = 0.f;
    for (int t = 0; t < SEQ_T; t++) s += p[(size_t)t * D_MODEL];
    g_pooled[idx] = s * (1.0f / SEQ_T);
}

// ---------------- 2. gate MLP + softmax ----------------
__global__ void gate_kernel(const float* __restrict__ Wg1, const float* __restrict__ bg1,
                            const float* __restrict__ Wg2, const float* __restrict__ bg2) {
    int b = blockIdx.x;
    int j = threadIdx.x;     // 128 threads
    __shared__ float h[GH];
    __shared__ float lg[NE];
    const float* p = g_pooled + b * D_MODEL;
    const float* w = Wg1 + (size_t)j * D_MODEL;
    float s = bg1[j];
    for (int i = 0; i < D_MODEL; i++) s += p[i] * w[i];
    h[j] = fmaxf(s, 0.f);
    __syncthreads();
    if (j < NE) {
        float s2 = bg2[j];
        const float* w2 = Wg2 + j * GH;
        for (int i = 0; i < GH; i++) s2 += h[i] * w2[i];
        lg[j] = s2;
    }
    __syncthreads();
    if (j == 0) {
        float m = lg[0];
        for (int e = 1; e < NE; e++) m = fmaxf(m, lg[e]);
        float ex[NE], sum = 0.f;
        for (int e = 0; e < NE; e++) { ex[e] = expf(lg[e] - m); sum += ex[e]; }
        float inv = 1.0f / sum;
        for (int e = 0; e < NE; e++) g_gw[b * NE + e] = ex[e] * inv;
    }
}

// ---------------- 3. mix expert weights:  W_eff[p][b] = sum_e gw[b,e] * W_p[e] ----------------
__global__ void mix_w_kernel(const float* __restrict__ Wq, const float* __restrict__ Wk,
                             const float* __restrict__ Wv) {
    int proj = blockIdx.y;
    size_t i = (size_t)blockIdx.x * 256 + threadIdx.x;   // over D*D
    const float* W = (proj == 0) ? Wq : (proj == 1) ? Wk : Wv;
    __shared__ float sgw[BATCH * NE];
    if (threadIdx.x < BATCH * NE) sgw[threadIdx.x] = g_gw[threadIdx.x];
    __syncthreads();
    float a0 = 0, a1 = 0, a2 = 0, a3 = 0;
    const size_t DD = (size_t)D_MODEL * D_MODEL;
    for (int e = 0; e < NE; e++) {
        float w = W[(size_t)e * DD + i];
        a0 += sgw[0 * NE + e] * w;
        a1 += sgw[1 * NE + e] * w;
        a2 += sgw[2 * NE + e] * w;
        a3 += sgw[3 * NE + e] * w;
    }
    float* o = g_Weff + (size_t)proj * BATCH * DD + i;
    o[0 * DD] = a0; o[1 * DD] = a1; o[2 * DD] = a2; o[3 * DD] = a3;
}

__global__ void mix_b_kernel(const float* __restrict__ bq, const float* __restrict__ bk,
                             const float* __restrict__ bv) {
    int idx = blockIdx.x * 256 + threadIdx.x;   // 3*B*D = 12288
    int proj = idx / (BATCH * D_MODEL);
    int r = idx % (BATCH * D_MODEL);
    int b = r / D_MODEL, o = r % D_MODEL;
    const float* bias = (proj == 0) ? bq : (proj == 1) ? bk : bv;
    float s = 0.f;
    for (int e = 0; e < NE; e++) s += g_gw[b * NE + e] * bias[e * D_MODEL + o];
    g_beff[idx] = s;
}

// ---------------- 4. SGEMM:  C = A @ Bw^T + bias   (A [M,K] rm, Bw [N,K] rm) ----------------
// QKVMODE: per-batch (grid.z = b), out written in [b,h,t,d] layout into g_Q/g_K/g_V.
// else:    single GEMM g_ctx @ Wo^T + bo -> Cx (plain row-major).
template <bool QKVMODE>
__global__ __launch_bounds__(256) void sgemm_kernel(const float* __restrict__ X,
                                                    const float* __restrict__ Wx,
                                                    const float* __restrict__ bx,
                                                    float* __restrict__ Cx, int which) {
    const int M = QKVMODE ? SEQ_T : BATCH * SEQ_T;
    const int N = D_MODEL, K = D_MODEL;
    int z = blockIdx.z;
    const float *A, *Bw, *bias;
    float* Cout;
    if (QKVMODE) {
        A = X + (size_t)z * M * K;
        Bw = g_Weff + ((size_t)which * BATCH + z) * D_MODEL * D_MODEL;
        bias = g_beff + (which * BATCH + z) * D_MODEL;
        Cout = ((which == 0) ? g_Q : (which == 1) ? g_K : g_V) + (size_t)z * NH * SEQ_T * DH;
    } else {
        A = g_ctx; Bw = Wx; bias = bx; Cout = Cx;
    }

    __shared__ float As[8][128];
    __shared__ float Bs[8][128];
    int tid = threadIdx.x;
    int row0 = (tid / 16) * 8, col0 = (tid % 16) * 8;
    int rowg = blockIdx.y * 128, colg = blockIdx.x * 128;
    int lr = tid >> 1, lc = (tid & 1) * 4;
    const float* Aptr = A + (size_t)(rowg + lr) * K + lc;
    const float* Bptr = Bw + (size_t)(colg + lr) * K + lc;

    float acc[8][8];
#pragma unroll
    for (int i = 0; i < 8; i++)
#pragma unroll
        for (int j = 0; j < 8; j++) acc[i][j] = 0.f;

    for (int k0 = 0; k0 < K; k0 += 8) {
        float4 av = *(const float4*)(Aptr + k0);
        float4 bv = *(const float4*)(Bptr + k0);
        As[lc + 0][lr] = av.x; As[lc + 1][lr] = av.y; As[lc + 2][lr] = av.z; As[lc + 3][lr] = av.w;
        Bs[lc + 0][lr] = bv.x; Bs[lc + 1][lr] = bv.y; Bs[lc + 2][lr] = bv.z; Bs[lc + 3][lr] = bv.w;
        __syncthreads();
#pragma unroll
        for (int k = 0; k < 8; k++) {
            float a[8], b[8];
            *(float4*)(a + 0) = *(const float4*)&As[k][row0];
            *(float4*)(a + 4) = *(const float4*)&As[k][row0 + 4];
            *(float4*)(b + 0) = *(const float4*)&Bs[k][col0];
            *(float4*)(b + 4) = *(const float4*)&Bs[k][col0 + 4];
#pragma unroll
            for (int i = 0; i < 8; i++)
#pragma unroll
                for (int j = 0; j < 8; j++) acc[i][j] += a[i] * b[j];
        }
        __syncthreads();
    }

#pragma unroll
    for (int i = 0; i < 8; i++) {
        int m = rowg + row0 + i;
#pragma unroll
        for (int j = 0; j < 8; j++) {
            int n = colg + col0 + j;
            float v = acc[i][j] + bias[n];
            if (QKVMODE)
                Cout[((size_t)(n >> 6) * SEQ_T + m) * DH + (n & 63)] = v;
            else
                Cout[(size_t)m * N + n] = v;
        }
    }
}

// ---------------- 5. flash attention, 64x64 tiles, fp32 ----------------
__global__ __launch_bounds__(256) void flash_kernel() {
    extern __shared__ float sm[];
    float* Qs = sm;                 // [64][64]
    float* Ks = sm + 64 * 64;       // [64][65]  (reused as P after softmax)
    float* Vs = Ks + 64 * 65;       // [64][64]

    int bh = blockIdx.y;
    int q0 = blockIdx.x * 64;
    const float* Qg = g_Q + (size_t)bh * SEQ_T * DH;
    const float* Kg = g_K + (size_t)bh * SEQ_T * DH;
    const float* Vg = g_V + (size_t)bh * SEQ_T * DH;

    int tid = threadIdx.x, tx = tid % 16, ty = tid / 16;

    // load Q tile (64x64 floats, float4)
#pragma unroll
    for (int u = 0; u < 4; u++) {
        int e = tid + u * 256;          // float4 index: 1024 total
        int r = e >> 4, c4 = (e & 15) * 4;
        *(float4*)&Qs[r * 64 + c4] = *(const float4*)&Qg[(size_t)(q0 + r) * DH + c4];
    }

    float mrow[4], lrow[4];
    float oacc[4][4];
#pragma unroll
    for (int i = 0; i < 4; i++) {
        mrow[i] = -1e30f; lrow[i] = 0.f;
#pragma unroll
        for (int j = 0; j < 4; j++) oacc[i][j] = 0.f;
    }

    for (int kt = 0; kt < SEQ_T; kt += 64) {
        // load K (padded 65) and V (64) tiles
#pragma unroll
        for (int u = 0; u < 4; u++) {
            int e = tid + u * 256;
            int r = e >> 4, c4 = (e & 15) * 4;
            float4 kv = *(const float4*)&Kg[(size_t)(kt + r) * DH + c4];
            Ks[r * 65 + c4 + 0] = kv.x; Ks[r * 65 + c4 + 1] = kv.y;
            Ks[r * 65 + c4 + 2] = kv.z; Ks[r * 65 + c4 + 3] = kv.w;
            *(float4*)&Vs[r * 64 + c4] = *(const float4*)&Vg[(size_t)(kt + r) * DH + c4];
        }
        __syncthreads();

        // S = Q K^T (each thread 4x4)
        float s[4][4];
#pragma unroll
        for (int i = 0; i < 4; i++)
#pragma unroll
            for (int j = 0; j < 4; j++) s[i][j] = 0.f;
#pragma unroll 8
        for (int d = 0; d < DH; d++) {
            float qf[4], kf[4];
#pragma unroll
            for (int i = 0; i < 4; i++) qf[i] = Qs[(ty * 4 + i) * 64 + d];
#pragma unroll
            for (int j = 0; j < 4; j++) kf[j] = Ks[(tx * 4 + j) * 65 + d];
#pragma unroll
            for (int i = 0; i < 4; i++)
#pragma unroll
                for (int j = 0; j < 4; j++) s[i][j] += qf[i] * kf[j];
        }

        // online softmax (row reduce across tx = 16 lanes within half-warp)
#pragma unroll
        for (int i = 0; i < 4; i++) {
            float rm = -1e30f;
#pragma unroll
            for (int j = 0; j < 4; j++) {
                s[i][j] *= 0.125f;                 // 1/sqrt(64)
                rm = fmaxf(rm, s[i][j]);
            }
#pragma unroll
            for (int off = 8; off >= 1; off >>= 1)
                rm = fmaxf(rm, __shfl_xor_sync(0xffffffffu, rm, off));
            float mnew = fmaxf(mrow[i], rm);
            float corr = __expf(mrow[i] - mnew);
            float rs = 0.f;
#pragma unroll
            for (int j = 0; j < 4; j++) {
                s[i][j] = __expf(s[i][j] - mnew);
                rs += s[i][j];
            }
#pragma unroll
            for (int off = 8; off >= 1; off >>= 1)
                rs += __shfl_xor_sync(0xffffffffu, rs, off);
            lrow[i] = lrow[i] * corr + rs;
            mrow[i] = mnew;
#pragma unroll
            for (int j = 0; j < 4; j++) oacc[i][j] *= corr;
        }
        __syncthreads();   // everyone done reading Ks

        // write P into Ks buffer: Ps[r][c], stride 65
#pragma unroll
        for (int i = 0; i < 4; i++)
#pragma unroll
            for (int j = 0; j < 4; j++)
                Ks[(ty * 4 + i) * 65 + tx * 4 + j] = s[i][j];
        __syncthreads();

        // O += P @ V
#pragma unroll 8
        for (int c = 0; c < 64; c++) {
            float pf[4], vf[4];
#pragma unroll
            for (int i = 0; i < 4; i++) pf[i] = Ks[(ty * 4 + i) * 65 + c];
            *(float4*)vf = *(const float4*)&Vs[c * 64 + tx * 4];
#pragma unroll
            for (int i = 0; i < 4; i++)
#pragma unroll
                for (int j = 0; j < 4; j++) oacc[i][j] += pf[i] * vf[j];
        }
        __syncthreads();
    }

    // normalize + write context in [b, t, h*64+col] layout
    int b = bh >> 4, h = bh & 15;
#pragma unroll
    for (int i = 0; i < 4; i++) {
        float inv = 1.0f / lrow[i];
        int t = q0 + ty * 4 + i;
        float4 v;
        v.x = oacc[i][0] * inv; v.y = oacc[i][1] * inv;
        v.z = oacc[i][2] * inv; v.w = oacc[i][3] * inv;
        *(float4*)&g_ctx[(size_t)(b * SEQ_T + t) * D_MODEL + h * DH + tx * 4] = v;
    }
}

// ---------------- launch ----------------
extern "C" void kernel_launch(void* const* d_in, const int* in_sizes, int n_in,
                              void* d_out, int out_size) {
    const float* x   = (const float*)d_in[0];
    const float* Wq  = (const float*)d_in[1];
    const float* bq  = (const float*)d_in[2];
    const float* Wk  = (const float*)d_in[3];
    const float* bk  = (const float*)d_in[4];
    const float* Wv  = (const float*)d_in[5];
    const float* bv  = (const float*)d_in[6];
    const float* Wg1 = (const float*)d_in[7];
    const float* bg1 = (const float*)d_in[8];
    const float* Wg2 = (const float*)d_in[9];
    const float* bg2 = (const float*)d_in[10];
    const float* Wo  = (const float*)d_in[11];
    const float* bo  = (const float*)d_in[12];
    float* out = (float*)d_out;

    pool_kernel<<<16, 256>>>(x);
    gate_kernel<<<4, 128>>>(Wg1, bg1, Wg2, bg2);
    mix_w_kernel<<<dim3(4096, 3), 256>>>(Wq, Wk, Wv);
    mix_b_kernel<<<48, 256>>>(bq, bk, bv);

    for (int p = 0; p < 3; p++)
        sgemm_kernel<true><<<dim3(8, 16, 4), 256>>>(x, nullptr, nullptr, nullptr, p);

    int smem = (64 * 64 + 64 * 65 + 64 * 64) * 4;   // 49408 B
    cudaFuncSetAttribute(flash_kernel, cudaFuncAttributeMaxDynamicSharedMemorySize, smem);
    flash_kernel<<<dim3(SEQ_T / 64, BATCH * NH), 256, smem>>>();

    sgemm_kernel<false><<<dim3(8, 64, 1), 256>>>(nullptr, Wo, bo, out, 0);
}

// round 16
// speedup vs baseline: 1.0025x; 1.0024x over previous
#include <cuda_runtime.h>

#define D_MODEL 1024
#define SEQ_T   2048
#define BATCH   4
#define NH      16
#define DH      64
#define NE      8
#define GH      128

// ---------------- static device scratch (no allocation allowed) ----------------
__device__ float g_pooled[BATCH * D_MODEL];
__device__ float g_gw[BATCH * NE];
__device__ float g_Weff[(size_t)3 * BATCH * D_MODEL * D_MODEL];   // ~50 MB
__device__ float g_beff[3 * BATCH * D_MODEL];
__device__ float g_Q[(size_t)BATCH * NH * SEQ_T * DH];
__device__ float g_K[(size_t)BATCH * NH * SEQ_T * DH];
__device__ float g_V[(size_t)BATCH * NH * SEQ_T * DH];
__device__ float g_ctx[(size_t)BATCH * SEQ_T * D_MODEL];

// ---------------- 1. mean pool over T ----------------
__global__ void pool_kernel(const float* __restrict__ x) {
    int idx = blockIdx.x * 256 + threadIdx.x;      // BATCH*D = 4096 threads
    int b = idx >> 10, c = idx & 1023;
    const float* p = x + (size_t)b * SEQ_T * D_MODEL + c;
    float s = 0.f;
    for (int t = 0; t < SEQ_T; t++) s += p[(size_t)t * D_MODEL];
    g_pooled[idx] = s * (1.0f / SEQ_T);
}

// ---------------- 2. gate MLP + softmax ----------------
__global__ void gate_kernel(const float* __restrict__ Wg1, const float* __restrict__ bg1,
                            const float* __restrict__ Wg2, const float* __restrict__ bg2) {
    int b = blockIdx.x;
    int j = threadIdx.x;     // 128 threads
    __shared__ float h[GH];
    __shared__ float lg[NE];
    const float* p = g_pooled + b * D_MODEL;
    const float* w = Wg1 + (size_t)j * D_MODEL;
    float s = bg1[j];
    for (int i = 0; i < D_MODEL; i++) s += p[i] * w[i];
    h[j] = fmaxf(s, 0.f);
    __syncthreads();
    if (j < NE) {
        float s2 = bg2[j];
        const float* w2 = Wg2 + j * GH;
        for (int i = 0; i < GH; i++) s2 += h[i] * w2[i];
        lg[j] = s2;
    }
    __syncthreads();
    if (j == 0) {
        float m = lg[0];
        for (int e = 1; e < NE; e++) m = fmaxf(m, lg[e]);
        float ex[NE], sum = 0.f;
        for (int e = 0; e < NE; e++) { ex[e] = expf(lg[e] - m); sum += ex[e]; }
        float inv = 1.0f / sum;
        for (int e = 0; e < NE; e++) g_gw[b * NE + e] = ex[e] * inv;
    }
}

// ---------------- 3. mix expert weights:  W_eff[p][b] = sum_e gw[b,e] * W_p[e] ----------------
__global__ void mix_w_kernel(const float* __restrict__ Wq, const float* __restrict__ Wk,
                             const float* __restrict__ Wv) {
    int proj = blockIdx.y;
    size_t i = (size_t)blockIdx.x * 256 + threadIdx.x;   // over D*D
    const float* W = (proj == 0) ? Wq : (proj == 1) ? Wk : Wv;
    __shared__ float sgw[BATCH * NE];
    if (threadIdx.x < BATCH * NE) sgw[threadIdx.x] = g_gw[threadIdx.x];
    __syncthreads();
    float a0 = 0, a1 = 0, a2 = 0, a3 = 0;
    const size_t DD = (size_t)D_MODEL * D_MODEL;
    for (int e = 0; e < NE; e++) {
        float w = W[(size_t)e * DD + i];
        a0 += sgw[0 * NE + e] * w;
        a1 += sgw[1 * NE + e] * w;
        a2 += sgw[2 * NE + e] * w;
        a3 += sgw[3 * NE + e] * w;
    }
    float* o = g_Weff + (size_t)proj * BATCH * DD + i;
    o[0 * DD] = a0; o[1 * DD] = a1; o[2 * DD] = a2; o[3 * DD] = a3;
}

__global__ void mix_b_kernel(const float* __restrict__ bq, const float* __restrict__ bk,
                             const float* __restrict__ bv) {
    int idx = blockIdx.x * 256 + threadIdx.x;   // 3*B*D = 12288
    int proj = idx / (BATCH * D_MODEL);
    int r = idx % (BATCH * D_MODEL);
    int b = r / D_MODEL, o = r % D_MODEL;
    const float* bias = (proj == 0) ? bq : (proj == 1) ? bk : bv;
    float s = 0.f;
    for (int e = 0; e < NE; e++) s += g_gw[b * NE + e] * bias[e * D_MODEL + o];
    g_beff[idx] = s;
}

// ---------------- 4. SGEMM:  C = A @ Bw^T + bias   (A [M,K] rm, Bw [N,K] rm) ----------------
// QKVMODE: per-batch (grid.z = b), out written in [b,h,t,d] layout into g_Q/g_K/g_V.
// else:    single GEMM g_ctx @ Wo^T + bo -> Cx (plain row-major).
template <bool QKVMODE>
__global__ __launch_bounds__(256) void sgemm_kernel(const float* __restrict__ X,
                                                    const float* __restrict__ Wx,
                                                    const float* __restrict__ bx,
                                                    float* __restrict__ Cx, int which) {
    const int M = QKVMODE ? SEQ_T : BATCH * SEQ_T;
    const int N = D_MODEL, K = D_MODEL;
    int z = blockIdx.z;
    const float *A, *Bw, *bias;
    float* Cout;
    if (QKVMODE) {
        A = X + (size_t)z * M * K;
        Bw = g_Weff + ((size_t)which * BATCH + z) * D_MODEL * D_MODEL;
        bias = g_beff + (which * BATCH + z) * D_MODEL;
        Cout = ((which == 0) ? g_Q : (which == 1) ? g_K : g_V) + (size_t)z * NH * SEQ_T * DH;
    } else {
        A = g_ctx; Bw = Wx; bias = bx; Cout = Cx;
    }

    __shared__ float As[8][128];
    __shared__ float Bs[8][128];
    int tid = threadIdx.x;
    int row0 = (tid / 16) * 8, col0 = (tid % 16) * 8;
    int rowg = blockIdx.y * 128, colg = blockIdx.x * 128;
    int lr = tid >> 1, lc = (tid & 1) * 4;
    const float* Aptr = A + (size_t)(rowg + lr) * K + lc;
    const float* Bptr = Bw + (size_t)(colg + lr) * K + lc;

    float acc[8][8];
#pragma unroll
    for (int i = 0; i < 8; i++)
#pragma unroll
        for (int j = 0; j < 8; j++) acc[i][j] = 0.f;

    for (int k0 = 0; k0 < K; k0 += 8) {
        float4 av = *(const float4*)(Aptr + k0);
        float4 bv = *(const float4*)(Bptr + k0);
        As[lc + 0][lr] = av.x; As[lc + 1][lr] = av.y; As[lc + 2][lr] = av.z; As[lc + 3][lr] = av.w;
        Bs[lc + 0][lr] = bv.x; Bs[lc + 1][lr] = bv.y; Bs[lc + 2][lr] = bv.z; Bs[lc + 3][lr] = bv.w;
        __syncthreads();
#pragma unroll
        for (int k = 0; k < 8; k++) {
            float a[8], b[8];
            *(float4*)(a + 0) = *(const float4*)&As[k][row0];
            *(float4*)(a + 4) = *(const float4*)&As[k][row0 + 4];
            *(float4*)(b + 0) = *(const float4*)&Bs[k][col0];
            *(float4*)(b + 4) = *(const float4*)&Bs[k][col0 + 4];
#pragma unroll
            for (int i = 0; i < 8; i++)
#pragma unroll
                for (int j = 0; j < 8; j++) acc[i][j] += a[i] * b[j];
        }
        __syncthreads();
    }

#pragma unroll
    for (int i = 0; i < 8; i++) {
        int m = rowg + row0 + i;
#pragma unroll
        for (int j = 0; j < 8; j++) {
            int n = colg + col0 + j;
            float v = acc[i][j] + bias[n];
            if (QKVMODE)
                Cout[((size_t)(n >> 6) * SEQ_T + m) * DH + (n & 63)] = v;
            else
                Cout[(size_t)m * N + n] = v;
        }
    }
}

// ---------------- 5. flash attention, 64x64 tiles, fp32 ----------------
__global__ __launch_bounds__(256) void flash_kernel() {
    extern __shared__ float sm[];
    float* Qs = sm;                 // [64][64]
    float* Ks = sm + 64 * 64;       // [64][65]  (reused as P after softmax)
    float* Vs = Ks + 64 * 65;       // [64][64]

    int bh = blockIdx.y;
    int q0 = blockIdx.x * 64;
    const float* Qg = g_Q + (size_t)bh * SEQ_T * DH;
    const float* Kg = g_K + (size_t)bh * SEQ_T * DH;
    const float* Vg = g_V + (size_t)bh * SEQ_T * DH;

    int tid = threadIdx.x, tx = tid % 16, ty = tid / 16;

    // load Q tile (64x64 floats, float4)
#pragma unroll
    for (int u = 0; u < 4; u++) {
        int e = tid + u * 256;          // float4 index: 1024 total
        int r = e >> 4, c4 = (e & 15) * 4;
        *(float4*)&Qs[r * 64 + c4] = *(const float4*)&Qg[(size_t)(q0 + r) * DH + c4];
    }

    float mrow[4], lrow[4];
    float oacc[4][4];
#pragma unroll
    for (int i = 0; i < 4; i++) {
        mrow[i] = -1e30f; lrow[i] = 0.f;
#pragma unroll
        for (int j = 0; j < 4; j++) oacc[i][j] = 0.f;
    }

    for (int kt = 0; kt < SEQ_T; kt += 64) {
        // load K (padded 65) and V (64) tiles
#pragma unroll
        for (int u = 0; u < 4; u++) {
            int e = tid + u * 256;
            int r = e >> 4, c4 = (e & 15) * 4;
            float4 kv = *(const float4*)&Kg[(size_t)(kt + r) * DH + c4];
            Ks[r * 65 + c4 + 0] = kv.x; Ks[r * 65 + c4 + 1] = kv.y;
            Ks[r * 65 + c4 + 2] = kv.z; Ks[r * 65 + c4 + 3] = kv.w;
            *(float4*)&Vs[r * 64 + c4] = *(const float4*)&Vg[(size_t)(kt + r) * DH + c4];
        }
        __syncthreads();

        // S = Q K^T (each thread 4x4)
        float s[4][4];
#pragma unroll
        for (int i = 0; i < 4; i++)
#pragma unroll
            for (int j = 0; j < 4; j++) s[i][j] = 0.f;
#pragma unroll 8
        for (int d = 0; d < DH; d++) {
            float qf[4], kf[4];
#pragma unroll
            for (int i = 0; i < 4; i++) qf[i] = Qs[(ty * 4 + i) * 64 + d];
#pragma unroll
            for (int j = 0; j < 4; j++) kf[j] = Ks[(tx * 4 + j) * 65 + d];
#pragma unroll
            for (int i = 0; i < 4; i++)
#pragma unroll
                for (int j = 0; j < 4; j++) s[i][j] += qf[i] * kf[j];
        }

        // online softmax (row reduce across tx = 16 lanes within half-warp)
#pragma unroll
        for (int i = 0; i < 4; i++) {
            float rm = -1e30f;
#pragma unroll
            for (int j = 0; j < 4; j++) {
                s[i][j] *= 0.125f;                 // 1/sqrt(64)
                rm = fmaxf(rm, s[i][j]);
            }
#pragma unroll
            for (int off = 8; off >= 1; off >>= 1)
                rm = fmaxf(rm, __shfl_xor_sync(0xffffffffu, rm, off));
            float mnew = fmaxf(mrow[i], rm);
            float corr = __expf(mrow[i] - mnew);
            float rs = 0.f;
#pragma unroll
            for (int j = 0; j < 4; j++) {
                s[i][j] = __expf(s[i][j] - mnew);
                rs += s[i][j];
            }
#pragma unroll
            for (int off = 8; off >= 1; off >>= 1)
                rs += __shfl_xor_sync(0xffffffffu, rs, off);
            lrow[i] = lrow[i] * corr + rs;
            mrow[i] = mnew;
#pragma unroll
            for (int j = 0; j < 4; j++) oacc[i][j] *= corr;
        }
        __syncthreads();   // everyone done reading Ks

        // write P into Ks buffer: Ps[r][c], stride 65
#pragma unroll
        for (int i = 0; i < 4; i++)
#pragma unroll
            for (int j = 0; j < 4; j++)
                Ks[(ty * 4 + i) * 65 + tx * 4 + j] = s[i][j];
        __syncthreads();

        // O += P @ V
#pragma unroll 8
        for (int c = 0; c < 64; c++) {
            float pf[4], vf[4];
#pragma unroll
            for (int i = 0; i < 4; i++) pf[i] = Ks[(ty * 4 + i) * 65 + c];
            *(float4*)vf = *(const float4*)&Vs[c * 64 + tx * 4];
#pragma unroll
            for (int i = 0; i < 4; i++)
#pragma unroll
                for (int j = 0; j < 4; j++) oacc[i][j] += pf[i] * vf[j];
        }
        __syncthreads();
    }

    // normalize + write context in [b, t, h*64+col] layout
    int b = bh >> 4, h = bh & 15;
#pragma unroll
    for (int i = 0; i < 4; i++) {
        float inv = 1.0f / lrow[i];
        int t = q0 + ty * 4 + i;
        float4 v;
        v.x = oacc[i][0] * inv; v.y = oacc[i][1] * inv;
        v.z = oacc[i][2] * inv; v.w = oacc[i][3] * inv;
        *(float4*)&g_ctx[(size_t)(b * SEQ_T + t) * D_MODEL + h * DH + tx * 4] = v;
    }
}

// ---------------- launch ----------------
extern "C" void kernel_launch(void* const* d_in, const int* in_sizes, int n_in,
                              void* d_out, int out_size) {
    const float* x   = (const float*)d_in[0];
    const float* Wq  = (const float*)d_in[1];
    const float* bq  = (const float*)d_in[2];
    const float* Wk  = (const float*)d_in[3];
    const float* bk  = (const float*)d_in[4];
    const float* Wv  = (const float*)d_in[5];
    const float* bv  = (const float*)d_in[6];
    const float* Wg1 = (const float*)d_in[7];
    const float* bg1 = (const float*)d_in[8];
    const float* Wg2 = (const float*)d_in[9];
    const float* bg2 = (const float*)d_in[10];
    const float* Wo  = (const float*)d_in[11];
    const float* bo  = (const float*)d_in[12];
    float* out = (float*)d_out;

    pool_kernel<<<16, 256>>>(x);
    gate_kernel<<<4, 128>>>(Wg1, bg1, Wg2, bg2);
    mix_w_kernel<<<dim3(4096, 3), 256>>>(Wq, Wk, Wv);
    mix_b_kernel<<<48, 256>>>(bq, bk, bv);

    for (int p = 0; p < 3; p++)
        sgemm_kernel<true><<<dim3(8, 16, 4), 256>>>(x, nullptr, nullptr, nullptr, p);

    int smem = (64 * 64 + 64 * 65 + 64 * 64) * 4;   // 49408 B
    cudaFuncSetAttribute(flash_kernel, cudaFuncAttributeMaxDynamicSharedMemorySize, smem);
    flash_kernel<<<dim3(SEQ_T / 64, BATCH * NH), 256, smem>>>();

    sgemm_kernel<false><<<dim3(8, 64, 1), 256>>>(nullptr, Wo, bo, out, 0);
}